// round 10
// baseline (speedup 1.0000x reference)
#include <cuda_runtime.h>
#include <cuda_bf16.h>

#define SEQ 2048
#define EMB 2048
#define NHEAD 32
#define HDIM 64
#define SCALING 0.125f

// Scratch buffers (allocation-free rule: __device__ globals)
__device__ float g_Q[SEQ * EMB];
__device__ float g_K[SEQ * EMB];
__device__ float g_V[SEQ * EMB];
__device__ float g_O[SEQ * EMB];

// ---------------------------------------------------------------------------
// helpers
// ---------------------------------------------------------------------------
__device__ __forceinline__ unsigned s2u(const void* p) {
    unsigned a;
    asm("{ .reg .u64 t; cvta.to.shared.u64 t, %1; cvt.u32.u64 %0, t; }"
        : "=r"(a) : "l"(p));
    return a;
}

// packed f32x2 FMA: lane-wise fp32 fma.rn (bitwise == 2 scalar FFMAs)
__device__ __forceinline__ unsigned long long ffma2(unsigned long long a,
                                                    unsigned long long b,
                                                    unsigned long long c) {
    unsigned long long d;
    asm("fma.rn.f32x2 %0, %1, %2, %3;" : "=l"(d) : "l"(a), "l"(b), "l"(c));
    return d;
}

// fp32 -> (tf32 hi, tf32 lo)
__device__ __forceinline__ void tf32split(float x, unsigned& hi, unsigned& lo) {
    unsigned h;
    asm("cvt.rna.tf32.f32 %0, %1;" : "=r"(h) : "f"(x));
    float r = x - __uint_as_float(h);
    asm("cvt.rna.tf32.f32 %0, %1;" : "=r"(lo) : "f"(r));
    hi = h;
}

// fp32 pair -> packed bf16x2 hi + packed bf16x2 residual (low half = a)
__device__ __forceinline__ void split2(float a, float b, unsigned& hi, unsigned& lo) {
    unsigned h;
    asm("cvt.rn.bf16x2.f32 %0, %1, %2;" : "=r"(h) : "f"(b), "f"(a));
    float ah = __uint_as_float(h << 16);
    float bh = __uint_as_float(h & 0xFFFF0000u);
    float ra = a - ah;
    float rb = b - bh;
    unsigned l;
    asm("cvt.rn.bf16x2.f32 %0, %1, %2;" : "=r"(l) : "f"(rb), "f"(ra));
    hi = h; lo = l;
}

#define MMA_TF32(C0, C1, C2, C3, A0, A1, A2, A3, B0, B1)                      \
    asm volatile(                                                             \
        "mma.sync.aligned.m16n8k8.row.col.f32.tf32.tf32.f32 "                 \
        "{%0,%1,%2,%3}, {%4,%5,%6,%7}, {%8,%9}, {%0,%1,%2,%3};"               \
        : "+f"(C0), "+f"(C1), "+f"(C2), "+f"(C3)                              \
        : "r"(A0), "r"(A1), "r"(A2), "r"(A3), "r"(B0), "r"(B1))

#define MMA_BF16(C0, C1, C2, C3, A0, A1, A2, A3, B0, B1)                      \
    asm volatile(                                                             \
        "mma.sync.aligned.m16n8k16.row.col.f32.bf16.bf16.f32 "                \
        "{%0,%1,%2,%3}, {%4,%5,%6,%7}, {%8,%9}, {%0,%1,%2,%3};"               \
        : "+f"(C0), "+f"(C1), "+f"(C2), "+f"(C3)                              \
        : "r"(A0), "r"(A1), "r"(A2), "r"(A3), "r"(B0), "r"(B1))

#define LDSM_X4(R0, R1, R2, R3, ADDR)                                         \
    asm volatile("ldmatrix.sync.aligned.m8n8.x4.shared.b16 {%0,%1,%2,%3}, [%4];" \
        : "=r"(R0), "=r"(R1), "=r"(R2), "=r"(R3) : "r"(ADDR))

#define LDSM_X2(R0, R1, ADDR)                                                 \
    asm volatile("ldmatrix.sync.aligned.m8n8.x2.shared.b16 {%0,%1}, [%2];"    \
        : "=r"(R0), "=r"(R1) : "r"(ADDR))

#define LDSM_X2_T(R0, R1, ADDR)                                               \
    asm volatile("ldmatrix.sync.aligned.m8n8.x2.trans.shared.b16 {%0,%1}, [%2];" \
        : "=r"(R0), "=r"(R1) : "r"(ADDR))

#define STS_V2(ADDR, V0, V1)                                                  \
    asm volatile("st.shared.v2.b32 [%0], {%1,%2};" :: "r"(ADDR), "r"(V0), "r"(V1) : "memory")

#define STS_V4(ADDR, V0, V1, V2, V3)                                          \
    asm volatile("st.shared.v4.b32 [%0], {%1,%2,%3,%4};"                      \
        :: "r"(ADDR), "r"(V0), "r"(V1), "r"(V2), "r"(V3) : "memory")

// ---------------------------------------------------------------------------
// 3-term TF32 GEMM (verified rounds 6/7) — Q and output projections.
// ---------------------------------------------------------------------------
#define ROW_B 144
#define TILE_B (128 * ROW_B)
#define STAGE_B (4 * TILE_B)
#define GEMM_SMEM (2 * STAGE_B)
#define NCH 64

__global__ __launch_bounds__(256, 1)
void gemm_mma_kernel(const float* __restrict__ A, const float* __restrict__ B,
                     const float* __restrict__ bias, float* __restrict__ C,
                     float scale)
{
    extern __shared__ char smem[];
    const unsigned sb = s2u(smem);
    const int tid = threadIdx.x;
    const int wid = tid >> 5;
    const int lane = tid & 31;
    const int wm = wid & 1;
    const int wn = wid >> 1;
    const int m0 = blockIdx.y * 128;
    const int n0 = blockIdx.x * 128;

    float acc[4][4][4];
#pragma unroll
    for (int i = 0; i < 4; i++)
#pragma unroll
        for (int j = 0; j < 4; j++)
#pragma unroll
            for (int r = 0; r < 4; r++) acc[i][j][r] = 0.f;

    float4 fa[4], fb[4];

    auto fetch = [&](int c) {
        const int k0 = c * 32;
#pragma unroll
        for (int u = 0; u < 4; u++) {
            int slot = tid + u * 256;
            int row = slot >> 3;
            int kq = (slot & 7) << 2;
            fa[u] = *(const float4*)&A[(size_t)(m0 + row) * EMB + k0 + kq];
            fb[u] = *(const float4*)&B[(size_t)(n0 + row) * EMB + k0 + kq];
        }
    };

    auto store_stage = [&](int s) {
        const unsigned base = sb + (unsigned)s * STAGE_B;
#pragma unroll
        for (int u = 0; u < 4; u++) {
            int slot = tid + u * 256;
            int row = slot >> 3;
            int kq = (slot & 7) << 2;
            unsigned off = (unsigned)(row * ROW_B + kq * 4);
            unsigned h0, h1, h2, h3, l0, l1, l2, l3;
            tf32split(fa[u].x, h0, l0); tf32split(fa[u].y, h1, l1);
            tf32split(fa[u].z, h2, l2); tf32split(fa[u].w, h3, l3);
            STS_V4(base + off, h0, h1, h2, h3);
            STS_V4(base + TILE_B + off, l0, l1, l2, l3);
            tf32split(fb[u].x, h0, l0); tf32split(fb[u].y, h1, l1);
            tf32split(fb[u].z, h2, l2); tf32split(fb[u].w, h3, l3);
            STS_V4(base + 2 * TILE_B + off, h0, h1, h2, h3);
            STS_V4(base + 3 * TILE_B + off, l0, l1, l2, l3);
        }
    };

    const unsigned a_rl = (unsigned)((lane & 7) + ((lane >> 3) & 1) * 8);
    const unsigned a_by = (unsigned)((lane >> 4) * 16);
    const unsigned b_rl = (unsigned)(lane & 7);
    const unsigned b_by = (unsigned)(((lane >> 3) & 1) * 16);

    fetch(0);
    store_stage(0);
    fetch(1);

#pragma unroll 1
    for (int c = 0; c < NCH; c++) {
        __syncthreads();
        if (c + 1 < NCH) store_stage((c + 1) & 1);
        if (c + 2 < NCH) fetch(c + 2);

        const unsigned abase = sb + (unsigned)(c & 1) * STAGE_B;
        const unsigned bbase = abase + 2 * TILE_B;

#pragma unroll
        for (int k8 = 0; k8 < 4; k8++) {
            const unsigned koff = (unsigned)(k8 * 32);
            unsigned Ah[4][4], Al[4][4], Bh[4][2], Bl[4][2];
#pragma unroll
            for (int mt = 0; mt < 4; mt++) {
                unsigned ad = abase + (wm * 64 + mt * 16 + a_rl) * ROW_B + a_by + koff;
                LDSM_X4(Ah[mt][0], Ah[mt][1], Ah[mt][2], Ah[mt][3], ad);
                LDSM_X4(Al[mt][0], Al[mt][1], Al[mt][2], Al[mt][3], ad + TILE_B);
            }
#pragma unroll
            for (int nt = 0; nt < 4; nt++) {
                unsigned bd = bbase + (wn * 32 + nt * 8 + b_rl) * ROW_B + b_by + koff;
                LDSM_X2(Bh[nt][0], Bh[nt][1], bd);
                LDSM_X2(Bl[nt][0], Bl[nt][1], bd + TILE_B);
            }
#pragma unroll
            for (int mt = 0; mt < 4; mt++)
#pragma unroll
                for (int nt = 0; nt < 4; nt++) {
                    float* cc = acc[mt][nt];
                    MMA_TF32(cc[0], cc[1], cc[2], cc[3],
                             Ah[mt][0], Ah[mt][1], Ah[mt][2], Ah[mt][3],
                             Bh[nt][0], Bh[nt][1]);
                    MMA_TF32(cc[0], cc[1], cc[2], cc[3],
                             Ah[mt][0], Ah[mt][1], Ah[mt][2], Ah[mt][3],
                             Bl[nt][0], Bl[nt][1]);
                    MMA_TF32(cc[0], cc[1], cc[2], cc[3],
                             Al[mt][0], Al[mt][1], Al[mt][2], Al[mt][3],
                             Bh[nt][0], Bh[nt][1]);
                }
        }
    }

    const int g = lane >> 2;
    const int c2 = (lane & 3) * 2;
#pragma unroll
    for (int mt = 0; mt < 4; mt++) {
        const int r0 = m0 + wm * 64 + mt * 16 + g;
#pragma unroll
        for (int nt = 0; nt < 4; nt++) {
            const int col = n0 + wn * 32 + nt * 8 + c2;
            float2 bv = *(const float2*)&bias[col];
            float2 o0, o1;
            o0.x = (acc[mt][nt][0] + bv.x) * scale;
            o0.y = (acc[mt][nt][1] + bv.y) * scale;
            o1.x = (acc[mt][nt][2] + bv.x) * scale;
            o1.y = (acc[mt][nt][3] + bv.y) * scale;
            *(float2*)&C[(size_t)r0 * EMB + col] = o0;
            *(float2*)&C[(size_t)(r0 + 8) * EMB + col] = o1;
        }
    }
}

// ---------------------------------------------------------------------------
// fp32 SIMT GEMM with packed f32x2 FMA — K and V projections.
// Per-accumulator op sequence identical to the verified scalar SIMT kernel
// (one fma.rn per k step, same order) -> bitwise-identical output.
// Bs2 holds duplicated (b,b) pairs, 18-float stride per tx slot so the 8
// LDS.64 per k hit 16 distinct banks (conflict-free; lanes 16-31 broadcast).
// ---------------------------------------------------------------------------
#define BM 128
#define BN 128
#define BK 16
#define GK 2048
#define B2ROW 288          // floats per Bs2 row (16 slots x 18)

__global__ __launch_bounds__(256) void gemm_nt_kernel(
    const float* __restrict__ A, const float* __restrict__ B,
    const float* __restrict__ bias, float* __restrict__ C, float scale)
{
    __shared__ float As[BK][BM];
    __shared__ float Bs2[BK][B2ROW];

    const int tid = threadIdx.x;
    const int tx = tid & 15;
    const int ty = tid >> 4;
    const int m0 = blockIdx.y * BM;
    const int n0 = blockIdx.x * BN;

    const unsigned sbA = s2u(&As[0][0]);
    const unsigned sbB = s2u(&Bs2[0][0]);

    unsigned long long acc2[4][8];     // [ipair][j] = (acc[2ip][j], acc[2ip+1][j])
#pragma unroll
    for (int ip = 0; ip < 4; ip++)
#pragma unroll
        for (int j = 0; j < 8; j++) acc2[ip][j] = 0ull;

    for (int kt = 0; kt < GK; kt += BK) {
#pragma unroll
        for (int u = 0; u < 2; u++) {
            int i = tid + u * 256;
            int row = i >> 2;               // 0..127
            int kq = (i & 3) << 2;          // 0,4,8,12
            float4 a = *(const float4*)&A[(size_t)(m0 + row) * GK + kt + kq];
            As[kq + 0][row] = a.x; As[kq + 1][row] = a.y;
            As[kq + 2][row] = a.z; As[kq + 3][row] = a.w;
            float4 b = *(const float4*)&B[(size_t)(n0 + row) * GK + kt + kq];
            // duplicated pair store: column 'row' lives in slot (row>>3), lane (row&7)
            unsigned boff = (unsigned)((row >> 3) * 18 + (row & 7) * 2);
            unsigned r;
            r = __float_as_uint(b.x);
            STS_V2(sbB + ((kq + 0) * B2ROW + boff) * 4, r, r);
            r = __float_as_uint(b.y);
            STS_V2(sbB + ((kq + 1) * B2ROW + boff) * 4, r, r);
            r = __float_as_uint(b.z);
            STS_V2(sbB + ((kq + 2) * B2ROW + boff) * 4, r, r);
            r = __float_as_uint(b.w);
            STS_V2(sbB + ((kq + 3) * B2ROW + boff) * 4, r, r);
        }
        __syncthreads();

#pragma unroll
        for (int k = 0; k < BK; k++) {
            // a pairs: (a0,a1),(a2,a3),(a4,a5),(a6,a7) directly from SMEM
            ulonglong2 ap01, ap23;
            asm volatile("ld.shared.v2.b64 {%0,%1}, [%2];"
                         : "=l"(ap01.x), "=l"(ap01.y)
                         : "r"(sbA + (k * BM + ty * 8) * 4));
            asm volatile("ld.shared.v2.b64 {%0,%1}, [%2];"
                         : "=l"(ap23.x), "=l"(ap23.y)
                         : "r"(sbA + (k * BM + ty * 8 + 4) * 4));
            unsigned long long ap[4] = {ap01.x, ap01.y, ap23.x, ap23.y};

            // duplicated b pairs for this thread's 8 columns
            unsigned long long bp[8];
            const unsigned bbase = sbB + (k * B2ROW + tx * 18) * 4;
#pragma unroll
            for (int j = 0; j < 8; j++)
                asm volatile("ld.shared.b64 %0, [%1];"
                             : "=l"(bp[j]) : "r"(bbase + j * 8));

#pragma unroll
            for (int ip = 0; ip < 4; ip++)
#pragma unroll
                for (int j = 0; j < 8; j++)
                    acc2[ip][j] = ffma2(ap[ip], bp[j], acc2[ip][j]);
        }
        __syncthreads();
    }

    // unpack to scalar accumulators (lo = even row, hi = odd row)
    float acc[8][8];
#pragma unroll
    for (int ip = 0; ip < 4; ip++)
#pragma unroll
        for (int j = 0; j < 8; j++) {
            acc[2 * ip][j]     = __uint_as_float((unsigned)(acc2[ip][j] & 0xffffffffull));
            acc[2 * ip + 1][j] = __uint_as_float((unsigned)(acc2[ip][j] >> 32));
        }

    float4 bv0 = *(const float4*)&bias[n0 + tx * 8];
    float4 bv1 = *(const float4*)&bias[n0 + tx * 8 + 4];
    float bb[8] = {bv0.x, bv0.y, bv0.z, bv0.w, bv1.x, bv1.y, bv1.z, bv1.w};

#pragma unroll
    for (int i = 0; i < 8; i++) {
        int row = m0 + ty * 8 + i;
        float4 o0, o1;
        o0.x = (acc[i][0] + bb[0]) * scale;
        o0.y = (acc[i][1] + bb[1]) * scale;
        o0.z = (acc[i][2] + bb[2]) * scale;
        o0.w = (acc[i][3] + bb[3]) * scale;
        o1.x = (acc[i][4] + bb[4]) * scale;
        o1.y = (acc[i][5] + bb[5]) * scale;
        o1.z = (acc[i][6] + bb[6]) * scale;
        o1.w = (acc[i][7] + bb[7]) * scale;
        *(float4*)&C[(size_t)row * GK + n0 + tx * 8] = o0;
        *(float4*)&C[(size_t)row * GK + n0 + tx * 8 + 4] = o1;
    }
}

// ---------------------------------------------------------------------------
// QuotRem fake quantize (verified)
// ---------------------------------------------------------------------------
__global__ __launch_bounds__(256) void quotrem_quantize_kernel(float* __restrict__ X)
{
    const int g = blockIdx.x * blockDim.x + threadIdx.x;
    if (g >= (SEQ * EMB) / 16) return;

    float4* p = (float4*)(X + (size_t)g * 16);
    float4 a = p[0], b = p[1], c = p[2], d = p[3];
    float x[16] = {a.x, a.y, a.z, a.w, b.x, b.y, b.z, b.w,
                   c.x, c.y, c.z, c.w, d.x, d.y, d.z, d.w};

    float mx = x[0], mn = x[0];
#pragma unroll
    for (int i = 1; i < 16; i++) {
        mx = fmaxf(mx, x[i]);
        mn = fminf(mn, x[i]);
    }
    float ma = fmaxf(fmaxf(mx, -mn), 1e-8f);

    float l2 = log2f(ma);
    float bflo = exp2f(floorf(l2));
    float bcei = exp2f(ceilf(l2));
    float base = (fabsf(ma - bflo) <= fabsf(bcei - ma)) ? bflo : bcei;
    base = fminf(fmaxf(base, 1.0f), 128.0f);

    float sign = (fabsf(mx) >= fabsf(mn)) ? 1.0f : -1.0f;
    float hb = 0.5f * base;
    float sb = sign * base;

    float qs[16], r[16];
    float mar = 0.f;
#pragma unroll
    for (int i = 0; i < 16; i++) {
        float q = (x[i] * sign >= hb) ? 1.0f : 0.0f;
        qs[i] = q * sb;
        r[i] = x[i] - qs[i];
        mar = fmaxf(mar, fabsf(r[i]));
    }
    mar = fmaxf(mar, 1e-8f);
    float sr = mar * (1.0f / 3.0f);

#pragma unroll
    for (int i = 0; i < 16; i++) {
        float rq = rintf(r[i] / sr);
        rq = fminf(fmaxf(rq, -4.0f), 3.0f);
        x[i] = qs[i] + rq * sr;
    }

    a.x = x[0];  a.y = x[1];  a.z = x[2];  a.w = x[3];
    b.x = x[4];  b.y = x[5];  b.z = x[6];  b.w = x[7];
    c.x = x[8];  c.y = x[9];  c.z = x[10]; c.w = x[11];
    d.x = x[12]; d.y = x[13]; d.z = x[14]; d.w = x[15];
    p[0] = a; p[1] = b; p[2] = c; p[3] = d;
}

// ---------------------------------------------------------------------------
// MMA causal flash attention (verified round 7)
// ---------------------------------------------------------------------------
#define FA_ROW 144
#define FA_TILE (64 * FA_ROW)
#define FA_STAGE (4 * FA_TILE)
#define FA_SMEM (2 * FA_STAGE)

__global__ __launch_bounds__(256, 1)
void flash_attn_mma_kernel(const float* __restrict__ Q, const float* __restrict__ K,
                           const float* __restrict__ V, float* __restrict__ O)
{
    extern __shared__ char smem[];
    const unsigned sb = s2u(smem);
    const int tid = threadIdx.x;
    const int wid = tid >> 5;
    const int lane = tid & 31;
    const int head = blockIdx.y;
    const int bx = (int)gridDim.x - 1 - (int)blockIdx.x;
    const int r0 = bx * 128;
    const int hb = head * HDIM;
    const int rw = r0 + wid * 16;
    const int g = lane >> 2;
    const int t = lane & 3;

#pragma unroll
    for (int u = 0; u < 8; u++) {
        int slot = tid + u * 256;
        int row = slot >> 4;
        int dq = (slot & 15) << 2;
        float4 v = *(const float4*)&Q[(size_t)(r0 + row) * EMB + hb + dq];
        unsigned h01, l01, h23, l23;
        split2(v.x, v.y, h01, l01);
        split2(v.z, v.w, h23, l23);
        unsigned off = (unsigned)(row * FA_ROW + dq * 2);
        STS_V2(sb + off, h01, h23);
        STS_V2(sb + 18432u + off, l01, l23);
    }
    __syncthreads();

    const unsigned a_rl = (unsigned)((lane & 7) + ((lane >> 3) & 1) * 8);
    const unsigned a_by = (unsigned)((lane >> 4) * 16);
    unsigned QH[4][4], QL[4][4];
#pragma unroll
    for (int kc = 0; kc < 4; kc++) {
        unsigned ad = sb + (wid * 16 + a_rl) * FA_ROW + kc * 32 + a_by;
        LDSM_X4(QH[kc][0], QH[kc][1], QH[kc][2], QH[kc][3], ad);
        LDSM_X4(QL[kc][0], QL[kc][1], QL[kc][2], QL[kc][3], ad + 18432u);
    }
    __syncthreads();

    float o[8][4];
#pragma unroll
    for (int j = 0; j < 8; j++)
#pragma unroll
        for (int r = 0; r < 4; r++) o[j][r] = 0.f;
    float m0r = -1e30f, m1r = -1e30f, l0 = 0.f, l1 = 0.f;

    const int ntiles = 2 * bx + 2;
    float4 fk[4], fv[4];

    auto fetchKV = [&](int tI) {
        const int c0 = tI * 64;
#pragma unroll
        for (int u = 0; u < 4; u++) {
            int slot = tid + u * 256;
            int kr = slot >> 4;
            int dq = (slot & 15) << 2;
            fk[u] = *(const float4*)&K[(size_t)(c0 + kr) * EMB + hb + dq];
            fv[u] = *(const float4*)&V[(size_t)(c0 + kr) * EMB + hb + dq];
        }
    };
    auto storeKV = [&](int s) {
        const unsigned base = sb + (unsigned)s * FA_STAGE;
#pragma unroll
        for (int u = 0; u < 4; u++) {
            int slot = tid + u * 256;
            int kr = slot >> 4;
            int dq = (slot & 15) << 2;
            unsigned off = (unsigned)(kr * FA_ROW + dq * 2);
            unsigned h01, l01, h23, l23;
            split2(fk[u].x, fk[u].y, h01, l01);
            split2(fk[u].z, fk[u].w, h23, l23);
            STS_V2(base + off, h01, h23);
            STS_V2(base + FA_TILE + off, l01, l23);
            split2(fv[u].x, fv[u].y, h01, l01);
            split2(fv[u].z, fv[u].w, h23, l23);
            STS_V2(base + 2 * FA_TILE + off, h01, h23);
            STS_V2(base + 3 * FA_TILE + off, l01, l23);
        }
    };

    fetchKV(0);
    storeKV(0);
    if (ntiles > 1) fetchKV(1);

#pragma unroll 1
    for (int c = 0; c < ntiles; c++) {
        __syncthreads();
        if (c + 1 < ntiles) storeKV((c + 1) & 1);
        if (c + 2 < ntiles) fetchKV(c + 2);

        const int c0 = c * 64;
        if (c0 <= rw + 15) {
            const unsigned kb = sb + (unsigned)(c & 1) * FA_STAGE;

            float s[8][4];
#pragma unroll
            for (int j = 0; j < 8; j++)
#pragma unroll
                for (int r = 0; r < 4; r++) s[j][r] = 0.f;

#pragma unroll
            for (int j = 0; j < 8; j++) {
                const unsigned bd = kb + (8 * j + (lane & 7)) * FA_ROW
                                  + ((lane >> 3) & 1) * 16;
#pragma unroll
                for (int kc = 0; kc < 4; kc++) {
                    unsigned bh0, bh1, bl0, bl1;
                    LDSM_X2(bh0, bh1, bd + kc * 32);
                    LDSM_X2(bl0, bl1, bd + kc * 32 + FA_TILE);
                    MMA_BF16(s[j][0], s[j][1], s[j][2], s[j][3],
                             QH[kc][0], QH[kc][1], QH[kc][2], QH[kc][3], bh0, bh1);
                    MMA_BF16(s[j][0], s[j][1], s[j][2], s[j][3],
                             QH[kc][0], QH[kc][1], QH[kc][2], QH[kc][3], bl0, bl1);
                    MMA_BF16(s[j][0], s[j][1], s[j][2], s[j][3],
                             QL[kc][0], QL[kc][1], QL[kc][2], QL[kc][3], bh0, bh1);
                }
            }

            if (c0 + 63 > rw) {
                const int rA = rw + g;
                const int rB = rw + g + 8;
#pragma unroll
                for (int j = 0; j < 8; j++) {
                    int col = c0 + 8 * j + 2 * t;
                    if (col > rA)     s[j][0] = -1e30f;
                    if (col + 1 > rA) s[j][1] = -1e30f;
                    if (col > rB)     s[j][2] = -1e30f;
                    if (col + 1 > rB) s[j][3] = -1e30f;
                }
            }

            float t0 = -1e30f, t1 = -1e30f;
#pragma unroll
            for (int j = 0; j < 8; j++) {
                t0 = fmaxf(t0, fmaxf(s[j][0], s[j][1]));
                t1 = fmaxf(t1, fmaxf(s[j][2], s[j][3]));
            }
            t0 = fmaxf(t0, __shfl_xor_sync(0xffffffff, t0, 1));
            t0 = fmaxf(t0, __shfl_xor_sync(0xffffffff, t0, 2));
            t1 = fmaxf(t1, __shfl_xor_sync(0xffffffff, t1, 1));
            t1 = fmaxf(t1, __shfl_xor_sync(0xffffffff, t1, 2));
            const float mn0 = fmaxf(m0r, t0);
            const float mn1 = fmaxf(m1r, t1);
            const float sc0 = __expf(m0r - mn0);
            const float sc1 = __expf(m1r - mn1);
            float sum0 = 0.f, sum1 = 0.f;
#pragma unroll
            for (int j = 0; j < 8; j++) {
                float p0 = __expf(s[j][0] - mn0);
                float p1 = __expf(s[j][1] - mn0);
                float p2 = __expf(s[j][2] - mn1);
                float p3 = __expf(s[j][3] - mn1);
                s[j][0] = p0; s[j][1] = p1; s[j][2] = p2; s[j][3] = p3;
                sum0 += p0 + p1;
                sum1 += p2 + p3;
            }
            sum0 += __shfl_xor_sync(0xffffffff, sum0, 1);
            sum0 += __shfl_xor_sync(0xffffffff, sum0, 2);
            sum1 += __shfl_xor_sync(0xffffffff, sum1, 1);
            sum1 += __shfl_xor_sync(0xffffffff, sum1, 2);
            l0 = l0 * sc0 + sum0;
            l1 = l1 * sc1 + sum1;
            m0r = mn0; m1r = mn1;
#pragma unroll
            for (int j = 0; j < 8; j++) {
                o[j][0] *= sc0; o[j][1] *= sc0;
                o[j][2] *= sc1; o[j][3] *= sc1;
            }

#pragma unroll
            for (int kc2 = 0; kc2 < 4; kc2++) {
                unsigned ph[4], pl[4];
                split2(s[2 * kc2][0],     s[2 * kc2][1],     ph[0], pl[0]);
                split2(s[2 * kc2][2],     s[2 * kc2][3],     ph[1], pl[1]);
                split2(s[2 * kc2 + 1][0], s[2 * kc2 + 1][1], ph[2], pl[2]);
                split2(s[2 * kc2 + 1][2], s[2 * kc2 + 1][3], ph[3], pl[3]);
                const unsigned vrow = kb + 2 * FA_TILE
                                    + (16 * kc2 + (lane & 15)) * FA_ROW;
#pragma unroll
                for (int j = 0; j < 8; j++) {
                    unsigned v0, v1, w0, w1;
                    LDSM_X2_T(v0, v1, vrow + j * 16);
                    LDSM_X2_T(w0, w1, vrow + j * 16 + FA_TILE);
                    MMA_BF16(o[j][0], o[j][1], o[j][2], o[j][3],
                             ph[0], ph[1], ph[2], ph[3], v0, v1);
                    MMA_BF16(o[j][0], o[j][1], o[j][2], o[j][3],
                             ph[0], ph[1], ph[2], ph[3], w0, w1);
                    MMA_BF16(o[j][0], o[j][1], o[j][2], o[j][3],
                             pl[0], pl[1], pl[2], pl[3], v0, v1);
                }
            }
        }
    }

    const float inv0 = 1.0f / l0;
    const float inv1 = 1.0f / l1;
    const int rA = rw + g;
    const int rB = rw + g + 8;
#pragma unroll
    for (int j = 0; j < 8; j++) {
        const int col = hb + 8 * j + 2 * t;
        float2 oa, ob;
        oa.x = o[j][0] * inv0; oa.y = o[j][1] * inv0;
        ob.x = o[j][2] * inv1; ob.y = o[j][3] * inv1;
        *(float2*)&O[(size_t)rA * EMB + col] = oa;
        *(float2*)&O[(size_t)rB * EMB + col] = ob;
    }
}

// ---------------------------------------------------------------------------
// Launch
// ---------------------------------------------------------------------------
extern "C" void kernel_launch(void* const* d_in, const int* in_sizes, int n_in,
                              void* d_out, int out_size)
{
    const float* X  = (const float*)d_in[0];
    const float* Wq = (const float*)d_in[1];
    const float* bq = (const float*)d_in[2];
    const float* Wk = (const float*)d_in[3];
    const float* bk = (const float*)d_in[4];
    const float* Wv = (const float*)d_in[5];
    const float* bv = (const float*)d_in[6];
    const float* Wo = (const float*)d_in[7];
    const float* bo = (const float*)d_in[8];
    float* out = (float*)d_out;

    void *pQ, *pK, *pV, *pO;
    cudaGetSymbolAddress(&pQ, g_Q);
    cudaGetSymbolAddress(&pK, g_K);
    cudaGetSymbolAddress(&pV, g_V);
    cudaGetSymbolAddress(&pO, g_O);
    float* Qb = (float*)pQ;
    float* Kb = (float*)pK;
    float* Vb = (float*)pV;
    float* Ob = (float*)pO;

    cudaFuncSetAttribute(gemm_mma_kernel,
                         cudaFuncAttributeMaxDynamicSharedMemorySize, GEMM_SMEM);
    cudaFuncSetAttribute(flash_attn_mma_kernel,
                         cudaFuncAttributeMaxDynamicSharedMemorySize, FA_SMEM);

    dim3 gg(EMB / 128, SEQ / 128);

    // Q projection: 3-term tf32 mma (verified)
    gemm_mma_kernel<<<gg, 256, GEMM_SMEM>>>(X, Wq, bq, Qb, SCALING);
    // K, V projections: fp32 FFMA2 SIMT (bitwise == verified scalar SIMT)
    gemm_nt_kernel<<<gg, 256>>>(X, Wk, bk, Kb, 1.0f);
    gemm_nt_kernel<<<gg, 256>>>(X, Wv, bv, Vb, 1.0f);

    const int ngroups = (SEQ * EMB) / 16;
    quotrem_quantize_kernel<<<ngroups / 256, 256>>>(Kb);
    quotrem_quantize_kernel<<<ngroups / 256, 256>>>(Vb);

    flash_attn_mma_kernel<<<dim3(SEQ / 128, NHEAD), 256, FA_SMEM>>>(Qb, Kb, Vb, Ob);

    // Output projection: 3-term tf32 mma (verified)
    gemm_mma_kernel<<<gg, 256, GEMM_SMEM>>>(Ob, Wo, bo, out, 1.0f);
}

// round 11
// speedup vs baseline: 1.3164x; 1.3164x over previous
#include <cuda_runtime.h>
#include <cuda_bf16.h>

#define SEQ 2048
#define EMB 2048
#define NHEAD 32
#define HDIM 64
#define SCALING 0.125f

// Scratch buffers (allocation-free rule: __device__ globals)
__device__ float g_Q[SEQ * EMB];
__device__ float g_K[SEQ * EMB];
__device__ float g_V[SEQ * EMB];
__device__ float g_O[SEQ * EMB];

// ---------------------------------------------------------------------------
// helpers
// ---------------------------------------------------------------------------
__device__ __forceinline__ unsigned s2u(const void* p) {
    unsigned a;
    asm("{ .reg .u64 t; cvta.to.shared.u64 t, %1; cvt.u32.u64 %0, t; }"
        : "=r"(a) : "l"(p));
    return a;
}

// fp32 pair -> packed bf16x2 hi + packed bf16x2 residual (low half = a)
__device__ __forceinline__ void split2(float a, float b, unsigned& hi, unsigned& lo) {
    unsigned h;
    asm("cvt.rn.bf16x2.f32 %0, %1, %2;" : "=r"(h) : "f"(b), "f"(a));
    float ah = __uint_as_float(h << 16);
    float bh = __uint_as_float(h & 0xFFFF0000u);
    float ra = a - ah;
    float rb = b - bh;
    unsigned l;
    asm("cvt.rn.bf16x2.f32 %0, %1, %2;" : "=r"(l) : "f"(rb), "f"(ra));
    hi = h; lo = l;
}

#define MMA_BF16(C0, C1, C2, C3, A0, A1, A2, A3, B0, B1)                      \
    asm volatile(                                                             \
        "mma.sync.aligned.m16n8k16.row.col.f32.bf16.bf16.f32 "                \
        "{%0,%1,%2,%3}, {%4,%5,%6,%7}, {%8,%9}, {%0,%1,%2,%3};"               \
        : "+f"(C0), "+f"(C1), "+f"(C2), "+f"(C3)                              \
        : "r"(A0), "r"(A1), "r"(A2), "r"(A3), "r"(B0), "r"(B1))

#define LDSM_X4(R0, R1, R2, R3, ADDR)                                         \
    asm volatile("ldmatrix.sync.aligned.m8n8.x4.shared.b16 {%0,%1,%2,%3}, [%4];" \
        : "=r"(R0), "=r"(R1), "=r"(R2), "=r"(R3) : "r"(ADDR))

#define LDSM_X2(R0, R1, ADDR)                                                 \
    asm volatile("ldmatrix.sync.aligned.m8n8.x2.shared.b16 {%0,%1}, [%2];"    \
        : "=r"(R0), "=r"(R1) : "r"(ADDR))

#define LDSM_X2_T(R0, R1, ADDR)                                               \
    asm volatile("ldmatrix.sync.aligned.m8n8.x2.trans.shared.b16 {%0,%1}, [%2];" \
        : "=r"(R0), "=r"(R1) : "r"(ADDR))

#define STS_V2(ADDR, V0, V1)                                                  \
    asm volatile("st.shared.v2.b32 [%0], {%1,%2};" :: "r"(ADDR), "r"(V0), "r"(V1) : "memory")

// ---------------------------------------------------------------------------
// bf16x3 GEMM via mma.sync — Q and output projections (smooth paths only).
// C = (A @ B^T + bias) * scale ; AhBh + AhBl + AlBh, fp32 accum.
// 128x128 CTA tile, BK=32, 8 warps (2m x 4n), warp tile 64x32.
// SMEM stage = Ah | Al | Bh | Bl, 128 rows x 40 bf16 (80 B, conflict-free
// ldmatrix phasing: 8-row bank phases {0,20,8,28,16,4,24,12}). 2 stages,
// single-sync double buffer: sync; store(c+1); fetch(c+2); compute(c).
// ---------------------------------------------------------------------------
#define ROW_B 80
#define TILE_B (128 * ROW_B)            // 10240
#define STAGE_B (4 * TILE_B)            // 40960
#define GEMM_SMEM (2 * STAGE_B)         // 81920
#define NCH 64

__global__ __launch_bounds__(256, 1)
void gemm_mma_kernel(const float* __restrict__ A, const float* __restrict__ B,
                     const float* __restrict__ bias, float* __restrict__ C,
                     float scale)
{
    extern __shared__ char smem[];
    const unsigned sb = s2u(smem);
    const int tid = threadIdx.x;
    const int wid = tid >> 5;
    const int lane = tid & 31;
    const int wm = wid & 1;
    const int wn = wid >> 1;
    const int m0 = blockIdx.y * 128;
    const int n0 = blockIdx.x * 128;

    float acc[4][4][4];
#pragma unroll
    for (int i = 0; i < 4; i++)
#pragma unroll
        for (int j = 0; j < 4; j++)
#pragma unroll
            for (int r = 0; r < 4; r++) acc[i][j][r] = 0.f;

    float4 fa[4], fb[4];

    auto fetch = [&](int c) {
        const int k0 = c * 32;
#pragma unroll
        for (int u = 0; u < 4; u++) {
            int slot = tid + u * 256;
            int row = slot >> 3;
            int kq = (slot & 7) << 2;
            fa[u] = *(const float4*)&A[(size_t)(m0 + row) * EMB + k0 + kq];
            fb[u] = *(const float4*)&B[(size_t)(n0 + row) * EMB + k0 + kq];
        }
    };

    auto store_stage = [&](int s) {
        const unsigned base = sb + (unsigned)s * STAGE_B;
#pragma unroll
        for (int u = 0; u < 4; u++) {
            int slot = tid + u * 256;
            int row = slot >> 3;
            int kq = (slot & 7) << 2;
            unsigned off = (unsigned)(row * ROW_B + kq * 2);
            unsigned h01, l01, h23, l23;
            split2(fa[u].x, fa[u].y, h01, l01);
            split2(fa[u].z, fa[u].w, h23, l23);
            STS_V2(base + off, h01, h23);
            STS_V2(base + TILE_B + off, l01, l23);
            split2(fb[u].x, fb[u].y, h01, l01);
            split2(fb[u].z, fb[u].w, h23, l23);
            STS_V2(base + 2 * TILE_B + off, h01, h23);
            STS_V2(base + 3 * TILE_B + off, l01, l23);
        }
    };

    // ldmatrix lane addressing (b16 tiles)
    const unsigned a_rl = (unsigned)((lane & 7) + ((lane >> 3) & 1) * 8);
    const unsigned a_by = (unsigned)((lane >> 4) * 16);
    const unsigned b_rl = (unsigned)(lane & 7);
    const unsigned b_by = (unsigned)(((lane >> 3) & 1) * 16);

    fetch(0);
    store_stage(0);
    fetch(1);

#pragma unroll 1
    for (int c = 0; c < NCH; c++) {
        __syncthreads();
        if (c + 1 < NCH) store_stage((c + 1) & 1);
        if (c + 2 < NCH) fetch(c + 2);

        const unsigned abase = sb + (unsigned)(c & 1) * STAGE_B;
        const unsigned bbase = abase + 2 * TILE_B;

#pragma unroll
        for (int k16 = 0; k16 < 32; k16 += 16) {
            unsigned Ah[4][4], Al[4][4], Bh[4][2], Bl[4][2];
#pragma unroll
            for (int mt = 0; mt < 4; mt++) {
                unsigned ad = abase + (wm * 64 + mt * 16 + a_rl) * ROW_B
                            + (k16 * 2 + a_by);
                LDSM_X4(Ah[mt][0], Ah[mt][1], Ah[mt][2], Ah[mt][3], ad);
                LDSM_X4(Al[mt][0], Al[mt][1], Al[mt][2], Al[mt][3], ad + TILE_B);
            }
#pragma unroll
            for (int nt = 0; nt < 4; nt++) {
                unsigned bd = bbase + (wn * 32 + nt * 8 + b_rl) * ROW_B
                            + (k16 * 2 + b_by);
                LDSM_X2(Bh[nt][0], Bh[nt][1], bd);
                LDSM_X2(Bl[nt][0], Bl[nt][1], bd + TILE_B);
            }
#pragma unroll
            for (int mt = 0; mt < 4; mt++)
#pragma unroll
                for (int nt = 0; nt < 4; nt++) {
                    float* cc = acc[mt][nt];
                    MMA_BF16(cc[0], cc[1], cc[2], cc[3],
                             Ah[mt][0], Ah[mt][1], Ah[mt][2], Ah[mt][3],
                             Bh[nt][0], Bh[nt][1]);
                    MMA_BF16(cc[0], cc[1], cc[2], cc[3],
                             Ah[mt][0], Ah[mt][1], Ah[mt][2], Ah[mt][3],
                             Bl[nt][0], Bl[nt][1]);
                    MMA_BF16(cc[0], cc[1], cc[2], cc[3],
                             Al[mt][0], Al[mt][1], Al[mt][2], Al[mt][3],
                             Bh[nt][0], Bh[nt][1]);
                }
        }
    }

    const int g = lane >> 2;
    const int c2 = (lane & 3) * 2;
#pragma unroll
    for (int mt = 0; mt < 4; mt++) {
        const int r0 = m0 + wm * 64 + mt * 16 + g;
#pragma unroll
        for (int nt = 0; nt < 4; nt++) {
            const int col = n0 + wn * 32 + nt * 8 + c2;
            float2 bv = *(const float2*)&bias[col];
            float2 o0, o1;
            o0.x = (acc[mt][nt][0] + bv.x) * scale;
            o0.y = (acc[mt][nt][1] + bv.y) * scale;
            o1.x = (acc[mt][nt][2] + bv.x) * scale;
            o1.y = (acc[mt][nt][3] + bv.y) * scale;
            *(float2*)&C[(size_t)r0 * EMB + col] = o0;
            *(float2*)&C[(size_t)(r0 + 8) * EMB + col] = o1;
        }
    }
}

// ---------------------------------------------------------------------------
// fp32 SIMT GEMM (VERIFIED round 2/6/7) — K and V projections.
// Sequential fp32 FFMA accumulation correlates with the reference's own
// rounding; the QuotRem quantizer amplifies any decorrelated K/V difference
// ~140x, so this exact kernel (bit-for-bit) is load-bearing. Do not replace.
// ---------------------------------------------------------------------------
#define BM 128
#define BN 128
#define BK 16
#define GK 2048

__global__ __launch_bounds__(256) void gemm_nt_kernel(
    const float* __restrict__ A, const float* __restrict__ B,
    const float* __restrict__ bias, float* __restrict__ C, float scale)
{
    __shared__ float As[BK][BM];
    __shared__ float Bs[BK][BN];

    const int tid = threadIdx.x;
    const int tx = tid & 15;
    const int ty = tid >> 4;
    const int m0 = blockIdx.y * BM;
    const int n0 = blockIdx.x * BN;

    float acc[8][8];
#pragma unroll
    for (int i = 0; i < 8; i++)
#pragma unroll
        for (int j = 0; j < 8; j++) acc[i][j] = 0.f;

    for (int kt = 0; kt < GK; kt += BK) {
#pragma unroll
        for (int u = 0; u < 2; u++) {
            int i = tid + u * 256;
            int row = i >> 2;
            int kq = (i & 3) << 2;
            float4 a = *(const float4*)&A[(size_t)(m0 + row) * GK + kt + kq];
            As[kq + 0][row] = a.x; As[kq + 1][row] = a.y;
            As[kq + 2][row] = a.z; As[kq + 3][row] = a.w;
            float4 b = *(const float4*)&B[(size_t)(n0 + row) * GK + kt + kq];
            Bs[kq + 0][row] = b.x; Bs[kq + 1][row] = b.y;
            Bs[kq + 2][row] = b.z; Bs[kq + 3][row] = b.w;
        }
        __syncthreads();

#pragma unroll
        for (int k = 0; k < BK; k++) {
            float4 a0 = *(const float4*)&As[k][ty * 8];
            float4 a1 = *(const float4*)&As[k][ty * 8 + 4];
            float4 b0 = *(const float4*)&Bs[k][tx * 8];
            float4 b1 = *(const float4*)&Bs[k][tx * 8 + 4];
            float ar[8] = {a0.x, a0.y, a0.z, a0.w, a1.x, a1.y, a1.z, a1.w};
            float br[8] = {b0.x, b0.y, b0.z, b0.w, b1.x, b1.y, b1.z, b1.w};
#pragma unroll
            for (int i = 0; i < 8; i++)
#pragma unroll
                for (int j = 0; j < 8; j++)
                    acc[i][j] += ar[i] * br[j];
        }
        __syncthreads();
    }

    float4 bv0 = *(const float4*)&bias[n0 + tx * 8];
    float4 bv1 = *(const float4*)&bias[n0 + tx * 8 + 4];
    float bb[8] = {bv0.x, bv0.y, bv0.z, bv0.w, bv1.x, bv1.y, bv1.z, bv1.w};

#pragma unroll
    for (int i = 0; i < 8; i++) {
        int row = m0 + ty * 8 + i;
        float4 o0, o1;
        o0.x = (acc[i][0] + bb[0]) * scale;
        o0.y = (acc[i][1] + bb[1]) * scale;
        o0.z = (acc[i][2] + bb[2]) * scale;
        o0.w = (acc[i][3] + bb[3]) * scale;
        o1.x = (acc[i][4] + bb[4]) * scale;
        o1.y = (acc[i][5] + bb[5]) * scale;
        o1.z = (acc[i][6] + bb[6]) * scale;
        o1.w = (acc[i][7] + bb[7]) * scale;
        *(float4*)&C[(size_t)row * GK + n0 + tx * 8] = o0;
        *(float4*)&C[(size_t)row * GK + n0 + tx * 8 + 4] = o1;
    }
}

// ---------------------------------------------------------------------------
// QuotRem fake quantize (verified)
// ---------------------------------------------------------------------------
__global__ __launch_bounds__(256) void quotrem_quantize_kernel(float* __restrict__ X)
{
    const int g = blockIdx.x * blockDim.x + threadIdx.x;
    if (g >= (SEQ * EMB) / 16) return;

    float4* p = (float4*)(X + (size_t)g * 16);
    float4 a = p[0], b = p[1], c = p[2], d = p[3];
    float x[16] = {a.x, a.y, a.z, a.w, b.x, b.y, b.z, b.w,
                   c.x, c.y, c.z, c.w, d.x, d.y, d.z, d.w};

    float mx = x[0], mn = x[0];
#pragma unroll
    for (int i = 1; i < 16; i++) {
        mx = fmaxf(mx, x[i]);
        mn = fminf(mn, x[i]);
    }
    float ma = fmaxf(fmaxf(mx, -mn), 1e-8f);

    float l2 = log2f(ma);
    float bflo = exp2f(floorf(l2));
    float bcei = exp2f(ceilf(l2));
    float base = (fabsf(ma - bflo) <= fabsf(bcei - ma)) ? bflo : bcei;
    base = fminf(fmaxf(base, 1.0f), 128.0f);

    float sign = (fabsf(mx) >= fabsf(mn)) ? 1.0f : -1.0f;
    float hb = 0.5f * base;
    float sb = sign * base;

    float qs[16], r[16];
    float mar = 0.f;
#pragma unroll
    for (int i = 0; i < 16; i++) {
        float q = (x[i] * sign >= hb) ? 1.0f : 0.0f;
        qs[i] = q * sb;
        r[i] = x[i] - qs[i];
        mar = fmaxf(mar, fabsf(r[i]));
    }
    mar = fmaxf(mar, 1e-8f);
    float sr = mar * (1.0f / 3.0f);

#pragma unroll
    for (int i = 0; i < 16; i++) {
        float rq = rintf(r[i] / sr);
        rq = fminf(fmaxf(rq, -4.0f), 3.0f);
        x[i] = qs[i] + rq * sr;
    }

    a.x = x[0];  a.y = x[1];  a.z = x[2];  a.w = x[3];
    b.x = x[4];  b.y = x[5];  b.z = x[6];  b.w = x[7];
    c.x = x[8];  c.y = x[9];  c.z = x[10]; c.w = x[11];
    d.x = x[12]; d.y = x[13]; d.z = x[14]; d.w = x[15];
    p[0] = a; p[1] = b; p[2] = c; p[3] = d;
}

// ---------------------------------------------------------------------------
// MMA causal flash attention (verified round 7)
// ---------------------------------------------------------------------------
#define FA_ROW 144
#define FA_TILE (64 * FA_ROW)
#define FA_STAGE (4 * FA_TILE)
#define FA_SMEM (2 * FA_STAGE)

__global__ __launch_bounds__(256, 1)
void flash_attn_mma_kernel(const float* __restrict__ Q, const float* __restrict__ K,
                           const float* __restrict__ V, float* __restrict__ O)
{
    extern __shared__ char smem[];
    const unsigned sb = s2u(smem);
    const int tid = threadIdx.x;
    const int wid = tid >> 5;
    const int lane = tid & 31;
    const int head = blockIdx.y;
    const int bx = (int)gridDim.x - 1 - (int)blockIdx.x;
    const int r0 = bx * 128;
    const int hb = head * HDIM;
    const int rw = r0 + wid * 16;
    const int g = lane >> 2;
    const int t = lane & 3;

#pragma unroll
    for (int u = 0; u < 8; u++) {
        int slot = tid + u * 256;
        int row = slot >> 4;
        int dq = (slot & 15) << 2;
        float4 v = *(const float4*)&Q[(size_t)(r0 + row) * EMB + hb + dq];
        unsigned h01, l01, h23, l23;
        split2(v.x, v.y, h01, l01);
        split2(v.z, v.w, h23, l23);
        unsigned off = (unsigned)(row * FA_ROW + dq * 2);
        STS_V2(sb + off, h01, h23);
        STS_V2(sb + 18432u + off, l01, l23);
    }
    __syncthreads();

    const unsigned a_rl = (unsigned)((lane & 7) + ((lane >> 3) & 1) * 8);
    const unsigned a_by = (unsigned)((lane >> 4) * 16);
    unsigned QH[4][4], QL[4][4];
#pragma unroll
    for (int kc = 0; kc < 4; kc++) {
        unsigned ad = sb + (wid * 16 + a_rl) * FA_ROW + kc * 32 + a_by;
        LDSM_X4(QH[kc][0], QH[kc][1], QH[kc][2], QH[kc][3], ad);
        LDSM_X4(QL[kc][0], QL[kc][1], QL[kc][2], QL[kc][3], ad + 18432u);
    }
    __syncthreads();

    float o[8][4];
#pragma unroll
    for (int j = 0; j < 8; j++)
#pragma unroll
        for (int r = 0; r < 4; r++) o[j][r] = 0.f;
    float m0r = -1e30f, m1r = -1e30f, l0 = 0.f, l1 = 0.f;

    const int ntiles = 2 * bx + 2;
    float4 fk[4], fv[4];

    auto fetchKV = [&](int tI) {
        const int c0 = tI * 64;
#pragma unroll
        for (int u = 0; u < 4; u++) {
            int slot = tid + u * 256;
            int kr = slot >> 4;
            int dq = (slot & 15) << 2;
            fk[u] = *(const float4*)&K[(size_t)(c0 + kr) * EMB + hb + dq];
            fv[u] = *(const float4*)&V[(size_t)(c0 + kr) * EMB + hb + dq];
        }
    };
    auto storeKV = [&](int s) {
        const unsigned base = sb + (unsigned)s * FA_STAGE;
#pragma unroll
        for (int u = 0; u < 4; u++) {
            int slot = tid + u * 256;
            int kr = slot >> 4;
            int dq = (slot & 15) << 2;
            unsigned off = (unsigned)(kr * FA_ROW + dq * 2);
            unsigned h01, l01, h23, l23;
            split2(fk[u].x, fk[u].y, h01, l01);
            split2(fk[u].z, fk[u].w, h23, l23);
            STS_V2(base + off, h01, h23);
            STS_V2(base + FA_TILE + off, l01, l23);
            split2(fv[u].x, fv[u].y, h01, l01);
            split2(fv[u].z, fv[u].w, h23, l23);
            STS_V2(base + 2 * FA_TILE + off, h01, h23);
            STS_V2(base + 3 * FA_TILE + off, l01, l23);
        }
    };

    fetchKV(0);
    storeKV(0);
    if (ntiles > 1) fetchKV(1);

#pragma unroll 1
    for (int c = 0; c < ntiles; c++) {
        __syncthreads();
        if (c + 1 < ntiles) storeKV((c + 1) & 1);
        if (c + 2 < ntiles) fetchKV(c + 2);

        const int c0 = c * 64;
        if (c0 <= rw + 15) {
            const unsigned kb = sb + (unsigned)(c & 1) * FA_STAGE;

            float s[8][4];
#pragma unroll
            for (int j = 0; j < 8; j++)
#pragma unroll
                for (int r = 0; r < 4; r++) s[j][r] = 0.f;

#pragma unroll
            for (int j = 0; j < 8; j++) {
                const unsigned bd = kb + (8 * j + (lane & 7)) * FA_ROW
                                  + ((lane >> 3) & 1) * 16;
#pragma unroll
                for (int kc = 0; kc < 4; kc++) {
                    unsigned bh0, bh1, bl0, bl1;
                    LDSM_X2(bh0, bh1, bd + kc * 32);
                    LDSM_X2(bl0, bl1, bd + kc * 32 + FA_TILE);
                    MMA_BF16(s[j][0], s[j][1], s[j][2], s[j][3],
                             QH[kc][0], QH[kc][1], QH[kc][2], QH[kc][3], bh0, bh1);
                    MMA_BF16(s[j][0], s[j][1], s[j][2], s[j][3],
                             QH[kc][0], QH[kc][1], QH[kc][2], QH[kc][3], bl0, bl1);
                    MMA_BF16(s[j][0], s[j][1], s[j][2], s[j][3],
                             QL[kc][0], QL[kc][1], QL[kc][2], QL[kc][3], bh0, bh1);
                }
            }

            if (c0 + 63 > rw) {
                const int rA = rw + g;
                const int rB = rw + g + 8;
#pragma unroll
                for (int j = 0; j < 8; j++) {
                    int col = c0 + 8 * j + 2 * t;
                    if (col > rA)     s[j][0] = -1e30f;
                    if (col + 1 > rA) s[j][1] = -1e30f;
                    if (col > rB)     s[j][2] = -1e30f;
                    if (col + 1 > rB) s[j][3] = -1e30f;
                }
            }

            float t0 = -1e30f, t1 = -1e30f;
#pragma unroll
            for (int j = 0; j < 8; j++) {
                t0 = fmaxf(t0, fmaxf(s[j][0], s[j][1]));
                t1 = fmaxf(t1, fmaxf(s[j][2], s[j][3]));
            }
            t0 = fmaxf(t0, __shfl_xor_sync(0xffffffff, t0, 1));
            t0 = fmaxf(t0, __shfl_xor_sync(0xffffffff, t0, 2));
            t1 = fmaxf(t1, __shfl_xor_sync(0xffffffff, t1, 1));
            t1 = fmaxf(t1, __shfl_xor_sync(0xffffffff, t1, 2));
            const float mn0 = fmaxf(m0r, t0);
            const float mn1 = fmaxf(m1r, t1);
            const float sc0 = __expf(m0r - mn0);
            const float sc1 = __expf(m1r - mn1);
            float sum0 = 0.f, sum1 = 0.f;
#pragma unroll
            for (int j = 0; j < 8; j++) {
                float p0 = __expf(s[j][0] - mn0);
                float p1 = __expf(s[j][1] - mn0);
                float p2 = __expf(s[j][2] - mn1);
                float p3 = __expf(s[j][3] - mn1);
                s[j][0] = p0; s[j][1] = p1; s[j][2] = p2; s[j][3] = p3;
                sum0 += p0 + p1;
                sum1 += p2 + p3;
            }
            sum0 += __shfl_xor_sync(0xffffffff, sum0, 1);
            sum0 += __shfl_xor_sync(0xffffffff, sum0, 2);
            sum1 += __shfl_xor_sync(0xffffffff, sum1, 1);
            sum1 += __shfl_xor_sync(0xffffffff, sum1, 2);
            l0 = l0 * sc0 + sum0;
            l1 = l1 * sc1 + sum1;
            m0r = mn0; m1r = mn1;
#pragma unroll
            for (int j = 0; j < 8; j++) {
                o[j][0] *= sc0; o[j][1] *= sc0;
                o[j][2] *= sc1; o[j][3] *= sc1;
            }

#pragma unroll
            for (int kc2 = 0; kc2 < 4; kc2++) {
                unsigned ph[4], pl[4];
                split2(s[2 * kc2][0],     s[2 * kc2][1],     ph[0], pl[0]);
                split2(s[2 * kc2][2],     s[2 * kc2][3],     ph[1], pl[1]);
                split2(s[2 * kc2 + 1][0], s[2 * kc2 + 1][1], ph[2], pl[2]);
                split2(s[2 * kc2 + 1][2], s[2 * kc2 + 1][3], ph[3], pl[3]);
                const unsigned vrow = kb + 2 * FA_TILE
                                    + (16 * kc2 + (lane & 15)) * FA_ROW;
#pragma unroll
                for (int j = 0; j < 8; j++) {
                    unsigned v0, v1, w0, w1;
                    LDSM_X2_T(v0, v1, vrow + j * 16);
                    LDSM_X2_T(w0, w1, vrow + j * 16 + FA_TILE);
                    MMA_BF16(o[j][0], o[j][1], o[j][2], o[j][3],
                             ph[0], ph[1], ph[2], ph[3], v0, v1);
                    MMA_BF16(o[j][0], o[j][1], o[j][2], o[j][3],
                             ph[0], ph[1], ph[2], ph[3], w0, w1);
                    MMA_BF16(o[j][0], o[j][1], o[j][2], o[j][3],
                             pl[0], pl[1], pl[2], pl[3], v0, v1);
                }
            }
        }
    }

    const float inv0 = 1.0f / l0;
    const float inv1 = 1.0f / l1;
    const int rA = rw + g;
    const int rB = rw + g + 8;
#pragma unroll
    for (int j = 0; j < 8; j++) {
        const int col = hb + 8 * j + 2 * t;
        float2 oa, ob;
        oa.x = o[j][0] * inv0; oa.y = o[j][1] * inv0;
        ob.x = o[j][2] * inv1; ob.y = o[j][3] * inv1;
        *(float2*)&O[(size_t)rA * EMB + col] = oa;
        *(float2*)&O[(size_t)rB * EMB + col] = ob;
    }
}

// ---------------------------------------------------------------------------
// Launch
// ---------------------------------------------------------------------------
extern "C" void kernel_launch(void* const* d_in, const int* in_sizes, int n_in,
                              void* d_out, int out_size)
{
    const float* X  = (const float*)d_in[0];
    const float* Wq = (const float*)d_in[1];
    const float* bq = (const float*)d_in[2];
    const float* Wk = (const float*)d_in[3];
    const float* bk = (const float*)d_in[4];
    const float* Wv = (const float*)d_in[5];
    const float* bv = (const float*)d_in[6];
    const float* Wo = (const float*)d_in[7];
    const float* bo = (const float*)d_in[8];
    float* out = (float*)d_out;

    void *pQ, *pK, *pV, *pO;
    cudaGetSymbolAddress(&pQ, g_Q);
    cudaGetSymbolAddress(&pK, g_K);
    cudaGetSymbolAddress(&pV, g_V);
    cudaGetSymbolAddress(&pO, g_O);
    float* Qb = (float*)pQ;
    float* Kb = (float*)pK;
    float* Vb = (float*)pV;
    float* Ob = (float*)pO;

    cudaFuncSetAttribute(gemm_mma_kernel,
                         cudaFuncAttributeMaxDynamicSharedMemorySize, GEMM_SMEM);
    cudaFuncSetAttribute(flash_attn_mma_kernel,
                         cudaFuncAttributeMaxDynamicSharedMemorySize, FA_SMEM);

    dim3 gg(EMB / 128, SEQ / 128);

    // Q projection: bf16x3 mma (smooth softmax path)
    gemm_mma_kernel<<<gg, 256, GEMM_SMEM>>>(X, Wq, bq, Qb, SCALING);
    // K, V projections: verified sequential-fp32 SIMT (quantizer-pinned)
    gemm_nt_kernel<<<gg, 256>>>(X, Wk, bk, Kb, 1.0f);
    gemm_nt_kernel<<<gg, 256>>>(X, Wv, bv, Vb, 1.0f);

    const int ngroups = (SEQ * EMB) / 16;
    quotrem_quantize_kernel<<<ngroups / 256, 256>>>(Kb);
    quotrem_quantize_kernel<<<ngroups / 256, 256>>>(Vb);

    flash_attn_mma_kernel<<<dim3(SEQ / 128, NHEAD), 256, FA_SMEM>>>(Qb, Kb, Vb, Ob);

    // Output projection: bf16x3 mma (smooth, directly measured)
    gemm_mma_kernel<<<gg, 256, GEMM_SMEM>>>(Ob, Wo, bo, out, 1.0f);
}